// round 4
// baseline (speedup 1.0000x reference)
#include <cuda_runtime.h>
#include <cuda_fp16.h>
#include <cstdint>

// Problem constants
#define TT   64
#define BB   4096
#define HH   256
#define BC   32            // batch rows per CTA
#define NCTA (BB / BC)     // 128 CTAs
#define SA_STRIDE 264      // halves per spike-matrix row (256 + 8 pad, 528B)

#define NSTAGE       4
#define CHUNK_U2     4096            // uint2 per chunk = 2 kt * (hi 1024 + lo 1024) = 32KB
#define CHUNK_BYTES  32768
#define TOTAL_CHUNKS (TT * 16)       // 16 chunks per timestep (2 layers * 8)

// __device__ scratch (no allocations allowed)
__device__ float d_emb [TT];
__device__ float d_val [TT * BB * 4];      // [t][b][c], c = {spk0,spk1,mem0,mem1}
// Packed weight fragments, streaming-friendly layout:
//   idx = ((l*16 + kt)*2 + s)*1024 + ntg*32 + lane
//   l: 0=W_h, 1=W_h2 ; s: 0=hi, 1=lo(*2048) ; uint2 = one lane's B-fragment (m16n8k16)
__device__ uint2 d_Wpack[65536];           // 512 KB

// ---------------------------------------------------------------------------
// Prep: pack split-fp16 weight fragments + temporal embedding
// ---------------------------------------------------------------------------
__global__ void prep_kernel(const float* __restrict__ W_h,
                            const float* __restrict__ W_h2)
{
    int idx  = blockIdx.x * 256 + threadIdx.x;     // 0 .. 65535
    int lane = idx & 31;
    int ntg  = (idx >> 5) & 31;
    int s    = (idx >> 10) & 1;
    int kt   = (idx >> 11) & 15;
    int l    = (idx >> 15) & 1;

    const float* W = l ? W_h2 : W_h;              // [n][k] row-major
    int n  = ntg * 8 + (lane >> 2);
    int k0 = kt * 16 + (lane & 3) * 2;

    __half h[4];
#pragma unroll
    for (int i = 0; i < 4; ++i) {
        int k = k0 + (i >> 1) * 8 + (i & 1);
        float w  = W[n * HH + k];
        __half hi = __float2half_rn(w);
        if (s == 0) h[i] = hi;
        else        h[i] = __float2half_rn((w - __half2float(hi)) * 2048.0f);
    }
    uint2 v;
    v.x = (uint32_t)__half_as_ushort(h[0]) | ((uint32_t)__half_as_ushort(h[1]) << 16);
    v.y = (uint32_t)__half_as_ushort(h[2]) | ((uint32_t)__half_as_ushort(h[3]) << 16);
    d_Wpack[idx] = v;

    if (blockIdx.x == 0 && threadIdx.x < TT) {
        int t = threadIdx.x;
        float p  = ((float)t - 32.0f) / 6.4f;
        float e  = expf(-0.5f * p * p);
        float e0 = expf(-0.5f * 25.0f);
        d_emb[t] = (e - e0) / (1.0f - e0);
    }
}

// ---------------------------------------------------------------------------
// PTX helpers
// ---------------------------------------------------------------------------
__device__ __forceinline__ void mma16816(float* d, const uint32_t* a, uint2 b) {
    asm volatile("mma.sync.aligned.m16n8k16.row.col.f32.f16.f16.f32 "
                 "{%0,%1,%2,%3},{%4,%5,%6,%7},{%8,%9},{%0,%1,%2,%3};"
                 : "+f"(d[0]), "+f"(d[1]), "+f"(d[2]), "+f"(d[3])
                 : "r"(a[0]), "r"(a[1]), "r"(a[2]), "r"(a[3]), "r"(b.x), "r"(b.y));
}
__device__ __forceinline__ void ldm4(uint32_t* r, const __half* p) {
    uint32_t addr = (uint32_t)__cvta_generic_to_shared(p);
    asm volatile("ldmatrix.sync.aligned.m8n8.x4.shared.b16 {%0,%1,%2,%3}, [%4];"
                 : "=r"(r[0]), "=r"(r[1]), "=r"(r[2]), "=r"(r[3]) : "r"(addr));
}
__device__ __forceinline__ void cp16(uint32_t dst, const void* src) {
    asm volatile("cp.async.ca.shared.global [%0], [%1], 16;" :: "r"(dst), "l"(src));
}
__device__ __forceinline__ void cp_commit() { asm volatile("cp.async.commit_group;"); }
template <int N> __device__ __forceinline__ void cp_wait() {
    asm volatile("cp.async.wait_group %0;" :: "n"(N));
}
__device__ __forceinline__ float clip01(float v) { return fminf(fmaxf(v, 0.f), 1.f); }

// Issue async copy of chunk c into the stage ring (all 256 threads; 128B each)
__device__ __forceinline__ void issue_chunk(int c, uint32_t stageBaseU32, int tid) {
    if (c < TOTAL_CHUNKS) {
        int cc = c & 15;                       // position within a timestep
        int l  = cc >> 3, ktp = cc & 7;
        const char* src = (const char*)d_Wpack
                        + ((size_t)(l * 16 + ktp * 2) * 2048) * sizeof(uint2)
                        + (size_t)tid * 16;
        uint32_t dst = stageBaseU32 + (uint32_t)(c & (NSTAGE - 1)) * CHUNK_BYTES + tid * 16;
#pragma unroll
        for (int i = 0; i < 8; ++i)
            cp16(dst + i * 4096, src + (size_t)i * 4096);
    }
    cp_commit();   // always commit (empty group keeps accounting aligned)
}

// ---------------------------------------------------------------------------
// One hidden layer: 8 chunk iterations of pipelined GEMM + LIF.
// Spikes staged fp16 in sIn; B-fragments come from the SMEM stage ring.
// ---------------------------------------------------------------------------
template <bool TOSMEM>
__device__ __forceinline__ void layer_gemm(
    const __half* __restrict__ sIn, __half* __restrict__ sOut, float* sp,
    float* mstate,
    const uint2* __restrict__ stages, uint32_t stageBaseU32, int& gc,
    const float* __restrict__ bias, const float* __restrict__ beta,
    const float* __restrict__ thr,
    int tid, int lane, int nbase)
{
    const int g = lane >> 2, q = lane & 3;
    float dh[32], dl[32];
#pragma unroll
    for (int i = 0; i < 32; ++i) { dh[i] = 0.f; dl[i] = 0.f; }

    const __half* aBase = sIn + (size_t)(lane & 15) * SA_STRIDE + (lane >> 4) * 8;
    const int ntg0 = nbase >> 3;

#pragma unroll 1
    for (int ci = 0; ci < 8; ++ci) {
        cp_wait<2>();          // chunk gc resident
        __syncthreads();       // all warps: data visible / prev buffer fully consumed
        issue_chunk(gc + 3, stageBaseU32, tid);

        const uint2* st = stages + (size_t)(gc & (NSTAGE - 1)) * CHUNK_U2;
#pragma unroll
        for (int ktl = 0; ktl < 2; ++ktl) {
            const uint2* hi = st + ktl * 2048;
            const uint2* lo = hi + 1024;
            uint2 bh[4], bl[4];
#pragma unroll
            for (int nt = 0; nt < 4; ++nt) {
                bh[nt] = hi[(ntg0 + nt) * 32 + lane];
                bl[nt] = lo[(ntg0 + nt) * 32 + lane];
            }
            uint32_t a[2][4];
            const int kt = ci * 2 + ktl;
#pragma unroll
            for (int mt = 0; mt < 2; ++mt)
                ldm4(a[mt], aBase + mt * 16 * SA_STRIDE + kt * 16);
#pragma unroll
            for (int nt = 0; nt < 4; ++nt)
#pragma unroll
                for (int mt = 0; mt < 2; ++mt) {
                    mma16816(&dh[(mt * 4 + nt) * 4], a[mt], bh[nt]);
                    mma16816(&dl[(mt * 4 + nt) * 4], a[mt], bl[nt]);
                }
        }
        gc++;
    }

    // LIF in fragment layout
#pragma unroll
    for (int mt = 0; mt < 2; ++mt)
#pragma unroll
        for (int nt = 0; nt < 4; ++nt) {
            int n0 = nbase + nt * 8 + q * 2;
            float2 bb = *(const float2*)(bias + n0);
            float2 be = *(const float2*)(beta + n0);
            float2 th = *(const float2*)(thr  + n0);
            float be0 = clip01(be.x), be1 = clip01(be.y);
#pragma unroll
            for (int rh = 0; rh < 2; ++rh) {
                int i0 = (mt * 4 + nt) * 4 + rh * 2;
                float cur0 = dh[i0]     + dl[i0]     * (1.f / 2048.f) + bb.x;
                float cur1 = dh[i0 + 1] + dl[i0 + 1] * (1.f / 2048.f) + bb.y;
                float mo0 = mstate[i0], mo1 = mstate[i0 + 1];
                float mn0 = be0 * mo0 + cur0 - ((mo0 > th.x) ? th.x : 0.f);
                float mn1 = be1 * mo1 + cur1 - ((mo1 > th.y) ? th.y : 0.f);
                mstate[i0] = mn0; mstate[i0 + 1] = mn1;
                float s0 = (mn0 > th.x) ? 1.f : 0.f;
                float s1 = (mn1 > th.y) ? 1.f : 0.f;
                if (TOSMEM) {
                    int row = mt * 16 + g + rh * 8;
                    *(__half2*)(sOut + (size_t)row * SA_STRIDE + n0) =
                        __floats2half2_rn(s0, s1);
                } else {
                    sp[i0] = s0; sp[i0 + 1] = s1;
                }
            }
        }
}

// ---------------------------------------------------------------------------
// Main recurrent kernel: T=64 loop, one CTA per 32 batch rows, 8 warps.
// Dynamic SMEM: [stage ring 128KB][sA 16.5KB][sB 16.5KB][m1 32KB][xs][red]
// ---------------------------------------------------------------------------
#define SMEM_STAGES   0
#define SMEM_SA       (NSTAGE * CHUNK_BYTES)                 // 131072
#define SMEM_SB       (SMEM_SA + BC * SA_STRIDE * 2)         // +16896
#define SMEM_M1       (SMEM_SB + BC * SA_STRIDE * 2)         // +16896
#define SMEM_XS       (SMEM_M1 + BC * HH * 4)                // +32768
#define SMEM_RED      (SMEM_XS + 2 * BC * 3 * 4)             // +768
#define SMEM_TOTAL    (SMEM_RED + BC * 2 * 8 * 4)            // +2048 => 200448

__global__ __launch_bounds__(256, 1) void snn_main_kernel(
    const float* __restrict__ x,
    const float* __restrict__ W_in,  const float* __restrict__ b_in,
    const float* __restrict__ beta_in, const float* __restrict__ thr_in,
    const float* __restrict__ b_h,   const float* __restrict__ beta_h, const float* __restrict__ thr_h,
    const float* __restrict__ b_h2,  const float* __restrict__ beta_h2, const float* __restrict__ thr_h2,
    const float* __restrict__ W_out, const float* __restrict__ b_out, const float* __restrict__ beta_out)
{
    extern __shared__ __align__(16) char dsm[];
    uint2*  stages = (uint2*)(dsm + SMEM_STAGES);
    __half* sA     = (__half*)(dsm + SMEM_SA);
    __half* sB     = (__half*)(dsm + SMEM_SB);
    float*  m1s    = (float*)(dsm + SMEM_M1);     // [b][j] thread-private slots
    float*  xs     = (float*)(dsm + SMEM_XS);     // [2][BC*3]
    float*  red    = (float*)(dsm + SMEM_RED);    // [BC][2][8]

    const uint32_t stageBaseU32 = (uint32_t)__cvta_generic_to_shared(stages);

    const int tid   = threadIdx.x;
    const int warp  = tid >> 5;
    const int lane  = tid & 31;
    const int g     = lane >> 2, q = lane & 3;
    const int bbase = blockIdx.x * BC;
    const int nbase = warp * 32;

    // layer-1 per-neuron constants (thread = neuron j)
    const int   j   = tid;
    const float Wi0 = W_in[j * 3 + 0], Wi1 = W_in[j * 3 + 1], Wi2 = W_in[j * 3 + 2];
    const float bin = b_in[j];
    const float betaIn = clip01(beta_in[j]);
    const float thrIn  = thr_in[j];

    float m2[32], m4[32];
#pragma unroll
    for (int i = 0; i < 32; ++i) { m2[i] = 0.f; m4[i] = 0.f; }
#pragma unroll
    for (int b = 0; b < BC; ++b) m1s[b * HH + j] = 0.f;   // thread-private, no sync needed

    // output-layer finisher (tid < 64): (b, o) = (tid>>1, tid&1)
    float m3r = 0.f, betaOutC = 0.f, bo = 0.f;
    const int fb = tid >> 1, fo = tid & 1;
    if (tid < 2 * BC) {
        betaOutC = clip01(beta_out[fo]);
        bo = b_out[fo];
    }

    // preload x(t=0); prime the cp.async ring with chunks 0..2
    float xreg = 0.f;
    if (tid < BC * 3) xreg = x[(size_t)bbase * 3 + tid];
    issue_chunk(0, stageBaseU32, tid);
    issue_chunk(1, stageBaseU32, tid);
    issue_chunk(2, stageBaseU32, tid);
    int gc = 0;

#pragma unroll 1
    for (int t = 0; t < TT; ++t) {
        if (tid < BC * 3) xs[(t & 1) * (BC * 3) + tid] = xreg;
        __syncthreads();                           // xs visible; red consumers done
        if (tid < BC * 3 && t + 1 < TT)
            xreg = x[((size_t)(t + 1) * BB + bbase) * 3 + tid];

        const float embt = d_emb[t];
        const float* xv = xs + (t & 1) * (BC * 3);

        // ---- layer 1 (input LIF), write spikes to sA ----
#pragma unroll
        for (int b = 0; b < BC; ++b) {
            float c1 = embt * (xv[b * 3] * Wi0 + xv[b * 3 + 1] * Wi1 + xv[b * 3 + 2] * Wi2) + bin;
            float mo = m1s[b * HH + j];
            float mn = betaIn * mo + c1 - ((mo > thrIn) ? thrIn : 0.f);
            m1s[b * HH + j] = mn;
            sA[b * SA_STRIDE + j] = __float2half_rn((mn > thrIn) ? 1.f : 0.f);
        }
        // (sA ready after the first chunk-iteration __syncthreads inside layer_gemm)

        // ---- layer 2: pipelined HMMA GEMM + LIF -> sB ----
        layer_gemm<true>(sA, sB, nullptr, m2, stages, stageBaseU32, gc,
                         b_h, beta_h, thr_h, tid, lane, nbase);

        // ---- layer 3: pipelined HMMA GEMM + LIF -> spikes in regs ----
        float sp[32];
        layer_gemm<false>(sB, nullptr, sp, m4, stages, stageBaseU32, gc,
                          b_h2, beta_h2, thr_h2, tid, lane, nbase);

        // ---- output partials: reduce this warp's n-range ----
#pragma unroll
        for (int mt = 0; mt < 2; ++mt)
#pragma unroll
            for (int rh = 0; rh < 2; ++rh) {
                float p0 = 0.f, p1 = 0.f;
#pragma unroll
                for (int nt = 0; nt < 4; ++nt) {
                    int n0 = nbase + nt * 8 + q * 2;
                    float2 w0 = *(const float2*)(W_out + n0);
                    float2 w1 = *(const float2*)(W_out + HH + n0);
                    int i0 = (mt * 4 + nt) * 4 + rh * 2;
                    p0 += sp[i0] * w0.x + sp[i0 + 1] * w0.y;
                    p1 += sp[i0] * w1.x + sp[i0 + 1] * w1.y;
                }
                p0 += __shfl_xor_sync(0xffffffffu, p0, 1);
                p0 += __shfl_xor_sync(0xffffffffu, p0, 2);
                p1 += __shfl_xor_sync(0xffffffffu, p1, 1);
                p1 += __shfl_xor_sync(0xffffffffu, p1, 2);
                if (q == 0) {
                    int row = mt * 16 + g + rh * 8;
                    red[(row * 2 + 0) * 8 + warp] = p0;
                    red[(row * 2 + 1) * 8 + warp] = p1;
                }
            }
        __syncthreads();                           // red ready

        // ---- leaky integrator (no reset), record spk & mem ----
        if (tid < 2 * BC) {
            float co = bo;
#pragma unroll
            for (int w = 0; w < 8; ++w) co += red[(fb * 2 + fo) * 8 + w];
            m3r = betaOutC * m3r + co;
            float spk = (m3r > 1.0f) ? 1.f : 0.f;
            size_t base = ((size_t)t * BB + bbase + fb) * 4;
            d_val[base + fo]     = spk;
            d_val[base + 2 + fo] = m3r;
        }
    }
}

// ---------------------------------------------------------------------------
// Final projection: flat d_val IS the reshaped [B, T*4] matrix.
// ---------------------------------------------------------------------------
__global__ void proj_kernel(const float* __restrict__ W_pred,
                            const float* __restrict__ b_pred,
                            float* __restrict__ out)
{
    int row  = blockIdx.x * 8 + (threadIdx.x >> 5);
    int lane = threadIdx.x & 31;
    const float* v = d_val + (size_t)row * 256;
    float p0 = 0.f, p1 = 0.f;
#pragma unroll
    for (int c = lane; c < 256; c += 32) {
        float vv = v[c];
        p0 += vv * W_pred[c];
        p1 += vv * W_pred[256 + c];
    }
#pragma unroll
    for (int off = 16; off > 0; off >>= 1) {
        p0 += __shfl_down_sync(0xffffffffu, p0, off);
        p1 += __shfl_down_sync(0xffffffffu, p1, off);
    }
    if (lane == 0) {
        out[row * 2 + 0] = p0 + b_pred[0];
        out[row * 2 + 1] = p1 + b_pred[1];
    }
}

// ---------------------------------------------------------------------------
extern "C" void kernel_launch(void* const* d_in, const int* in_sizes, int n_in,
                              void* d_out, int out_size)
{
    const float* x       = (const float*)d_in[0];
    const float* W_in    = (const float*)d_in[1];
    const float* b_in    = (const float*)d_in[2];
    const float* beta_in = (const float*)d_in[3];
    const float* thr_in  = (const float*)d_in[4];
    const float* W_h     = (const float*)d_in[5];
    const float* b_h     = (const float*)d_in[6];
    const float* beta_h  = (const float*)d_in[7];
    const float* thr_h   = (const float*)d_in[8];
    const float* W_h2    = (const float*)d_in[9];
    const float* b_h2    = (const float*)d_in[10];
    const float* beta_h2 = (const float*)d_in[11];
    const float* thr_h2  = (const float*)d_in[12];
    const float* W_out   = (const float*)d_in[13];
    const float* b_out   = (const float*)d_in[14];
    const float* beta_out= (const float*)d_in[15];
    const float* W_pred  = (const float*)d_in[16];
    const float* b_pred  = (const float*)d_in[17];
    float* out = (float*)d_out;

    cudaFuncSetAttribute(snn_main_kernel,
                         cudaFuncAttributeMaxDynamicSharedMemorySize, SMEM_TOTAL);

    prep_kernel<<<256, 256>>>(W_h, W_h2);
    snn_main_kernel<<<NCTA, 256, SMEM_TOTAL>>>(x, W_in, b_in, beta_in, thr_in,
                                               b_h, beta_h, thr_h,
                                               b_h2, beta_h2, thr_h2,
                                               W_out, b_out, beta_out);
    proj_kernel<<<BB / 8, 256>>>(W_pred, b_pred, out);
}

// round 6
// speedup vs baseline: 1.7589x; 1.7589x over previous
#include <cuda_runtime.h>
#include <cuda_fp16.h>
#include <cstdint>

// Problem constants
#define TT   64
#define BB   4096
#define HH   256
#define BC   32            // batch rows per CTA
#define NCTA (BB / BC)     // 128 CTAs
#define SA_STRIDE 264      // halves per spike-row (256 + 8 pad)

// __device__ scratch (no allocations allowed)
__device__ float d_emb [TT];
__device__ float d_val [TT * BB * 4];      // [t][b][c], c = {spk0,spk1,mem0,mem1}
// Packed weight fragments: idx = (l*2+s)*16384 + kt*1024 + ntg*32 + lane
//   l: 0=W_h, 1=W_h2 ; s: 0=hi, 1=lo(*2048)
//   uint2 = one lane's B-fragment for mma.m16n8k16
__device__ uint2 d_Wpack[65536];           // 512 KB

// ---------------------------------------------------------------------------
// Prep: pack split-fp16 weight fragments + temporal embedding
// ---------------------------------------------------------------------------
__global__ void prep_kernel(const float* __restrict__ W_h,
                            const float* __restrict__ W_h2)
{
    int idx  = blockIdx.x * 256 + threadIdx.x;     // 0 .. 65535
    int lane = idx & 31;
    int ntg  = (idx >> 5) & 31;
    int kt   = (idx >> 10) & 15;
    int s    = (idx >> 14) & 1;
    int l    = (idx >> 15) & 1;

    const float* W = l ? W_h2 : W_h;              // [n][k] row-major
    int n  = ntg * 8 + (lane >> 2);
    int k0 = kt * 16 + (lane & 3) * 2;

    __half h[4];
#pragma unroll
    for (int i = 0; i < 4; ++i) {
        int k = k0 + (i >> 1) * 8 + (i & 1);
        float w  = W[n * HH + k];
        __half hi = __float2half_rn(w);
        if (s == 0) h[i] = hi;
        else        h[i] = __float2half_rn((w - __half2float(hi)) * 2048.0f);
    }
    uint2 v;
    v.x = (uint32_t)__half_as_ushort(h[0]) | ((uint32_t)__half_as_ushort(h[1]) << 16);
    v.y = (uint32_t)__half_as_ushort(h[2]) | ((uint32_t)__half_as_ushort(h[3]) << 16);
    d_Wpack[idx] = v;

    if (blockIdx.x == 0 && threadIdx.x < TT) {
        int t = threadIdx.x;
        float p  = ((float)t - 32.0f) / 6.4f;
        float e  = expf(-0.5f * p * p);
        float e0 = expf(-0.5f * 25.0f);
        d_emb[t] = (e - e0) / (1.0f - e0);
    }
}

// ---------------------------------------------------------------------------
// PTX helpers
// ---------------------------------------------------------------------------
__device__ __forceinline__ void mma16816(float* d, const uint32_t* a, uint2 b) {
    asm volatile("mma.sync.aligned.m16n8k16.row.col.f32.f16.f16.f32 "
                 "{%0,%1,%2,%3},{%4,%5,%6,%7},{%8,%9},{%0,%1,%2,%3};"
                 : "+f"(d[0]), "+f"(d[1]), "+f"(d[2]), "+f"(d[3])
                 : "r"(a[0]), "r"(a[1]), "r"(a[2]), "r"(a[3]), "r"(b.x), "r"(b.y));
}
__device__ __forceinline__ void ldm4(uint32_t* r, const __half* p) {
    uint32_t addr = (uint32_t)__cvta_generic_to_shared(p);
    asm volatile("ldmatrix.sync.aligned.m8n8.x4.shared.b16 {%0,%1,%2,%3}, [%4];"
                 : "=r"(r[0]), "=r"(r[1]), "=r"(r[2]), "=r"(r[3]) : "r"(addr));
}
// L1-pinned load (lines survive streaming pollution)
__device__ __forceinline__ uint2 ldg_keep(const uint2* p) {
    uint2 v;
    asm volatile("ld.global.nc.L1::evict_last.v2.u32 {%0,%1}, [%2];"
                 : "=r"(v.x), "=r"(v.y) : "l"(p));
    return v;
}
// Streaming load (evicted first; protects the pinned set)
__device__ __forceinline__ uint2 ldg_stream(const uint2* p) {
    uint2 v;
    asm volatile("ld.global.nc.L1::evict_first.v2.u32 {%0,%1}, [%2];"
                 : "=r"(v.x), "=r"(v.y) : "l"(p));
    return v;
}
__device__ __forceinline__ float clip01(float v) { return fminf(fmaxf(v, 0.f), 1.f); }

// ---------------------------------------------------------------------------
// One hidden layer: split-fp16 HMMA GEMM (separate hi/lo fp32 accumulators,
// round-3 arithmetic) + LIF. B fragments ping-pong double-buffered in regs,
// prefetched one kt ahead — no barriers.
// PINHI: hi stream gets L1::evict_last (stays resident across all 64 steps).
// ---------------------------------------------------------------------------
template <bool TOSMEM, bool PINHI>
__device__ __forceinline__ void layer_gemm(
    const __half* __restrict__ sIn, __half* __restrict__ sOut, float* sp,
    float* mstate,
    const uint2* __restrict__ packHi, const uint2* __restrict__ packLo,
    const float* __restrict__ bias, const float* __restrict__ beta,
    const float* __restrict__ thr,
    int lane, int nbase)
{
    const int g = lane >> 2, q = lane & 3;
    float dh[32], dl[32];
#pragma unroll
    for (int i = 0; i < 32; ++i) { dh[i] = 0.f; dl[i] = 0.f; }

    const __half* aBase = sIn + (size_t)(lane & 15) * SA_STRIDE + (lane >> 4) * 8;
    const uint2* pHi = packHi + ((nbase >> 3) * 32 + lane);   // + kt*1024 + nt*32
    const uint2* pLo = packLo + ((nbase >> 3) * 32 + lane);

    uint2 bhA[4], blA[4], bhB[4], blB[4];
#pragma unroll
    for (int nt = 0; nt < 4; ++nt) {
        bhA[nt] = PINHI ? ldg_keep(pHi + nt * 32) : ldg_stream(pHi + nt * 32);
        blA[nt] = ldg_stream(pLo + nt * 32);
    }
#pragma unroll
    for (int nt = 0; nt < 4; ++nt) {
        bhB[nt] = PINHI ? ldg_keep(pHi + 1024 + nt * 32) : ldg_stream(pHi + 1024 + nt * 32);
        blB[nt] = ldg_stream(pLo + 1024 + nt * 32);
    }

#pragma unroll 2
    for (int kt = 0; kt < 16; kt += 2) {
        uint32_t a[2][4];
        // kt (even): consume A buffers
#pragma unroll
        for (int mt = 0; mt < 2; ++mt)
            ldm4(a[mt], aBase + mt * 16 * SA_STRIDE + kt * 16);
#pragma unroll
        for (int nt = 0; nt < 4; ++nt)
#pragma unroll
            for (int mt = 0; mt < 2; ++mt) {
                mma16816(&dh[(mt * 4 + nt) * 4], a[mt], bhA[nt]);
                mma16816(&dl[(mt * 4 + nt) * 4], a[mt], blA[nt]);
            }
        if (kt + 2 < 16) {
#pragma unroll
            for (int nt = 0; nt < 4; ++nt) {
                bhA[nt] = PINHI ? ldg_keep(pHi + (kt + 2) * 1024 + nt * 32)
                                : ldg_stream(pHi + (kt + 2) * 1024 + nt * 32);
                blA[nt] = ldg_stream(pLo + (kt + 2) * 1024 + nt * 32);
            }
        }
        // kt+1 (odd): consume B buffers
#pragma unroll
        for (int mt = 0; mt < 2; ++mt)
            ldm4(a[mt], aBase + mt * 16 * SA_STRIDE + (kt + 1) * 16);
#pragma unroll
        for (int nt = 0; nt < 4; ++nt)
#pragma unroll
            for (int mt = 0; mt < 2; ++mt) {
                mma16816(&dh[(mt * 4 + nt) * 4], a[mt], bhB[nt]);
                mma16816(&dl[(mt * 4 + nt) * 4], a[mt], blB[nt]);
            }
        if (kt + 3 < 16) {
#pragma unroll
            for (int nt = 0; nt < 4; ++nt) {
                bhB[nt] = PINHI ? ldg_keep(pHi + (kt + 3) * 1024 + nt * 32)
                                : ldg_stream(pHi + (kt + 3) * 1024 + nt * 32);
                blB[nt] = ldg_stream(pLo + (kt + 3) * 1024 + nt * 32);
            }
        }
    }

    // LIF in fragment layout (round-3 arithmetic: dh + dl/2048 + bias)
#pragma unroll
    for (int mt = 0; mt < 2; ++mt)
#pragma unroll
        for (int nt = 0; nt < 4; ++nt) {
            int n0 = nbase + nt * 8 + q * 2;
            float2 bb = *(const float2*)(bias + n0);
            float2 be = *(const float2*)(beta + n0);
            float2 th = *(const float2*)(thr  + n0);
            float be0 = clip01(be.x), be1 = clip01(be.y);
#pragma unroll
            for (int rh = 0; rh < 2; ++rh) {
                int i0 = (mt * 4 + nt) * 4 + rh * 2;
                float cur0 = dh[i0]     + dl[i0]     * (1.f / 2048.f) + bb.x;
                float cur1 = dh[i0 + 1] + dl[i0 + 1] * (1.f / 2048.f) + bb.y;
                float mo0 = mstate[i0], mo1 = mstate[i0 + 1];
                float mn0 = be0 * mo0 + cur0 - ((mo0 > th.x) ? th.x : 0.f);
                float mn1 = be1 * mo1 + cur1 - ((mo1 > th.y) ? th.y : 0.f);
                mstate[i0] = mn0; mstate[i0 + 1] = mn1;
                float s0 = (mn0 > th.x) ? 1.f : 0.f;
                float s1 = (mn1 > th.y) ? 1.f : 0.f;
                if (TOSMEM) {
                    int row = mt * 16 + g + rh * 8;
                    *(__half2*)(sOut + (size_t)row * SA_STRIDE + n0) =
                        __floats2half2_rn(s0, s1);
                } else {
                    sp[i0] = s0; sp[i0 + 1] = s1;
                }
            }
        }
}

// ---------------------------------------------------------------------------
// Dynamic SMEM layout
// ---------------------------------------------------------------------------
#define SMEM_SA   0
#define SMEM_SB   (SMEM_SA + BC * SA_STRIDE * 2)      // 16896
#define SMEM_M1   (SMEM_SB + BC * SA_STRIDE * 2)      // 33792
#define SMEM_XS   (SMEM_M1 + BC * HH * 4)             // 66560
#define SMEM_RED  (SMEM_XS + 2 * BC * 3 * 4)          // 67328
#define SMEM_TOTAL (SMEM_RED + BC * 2 * 8 * 4)        // 69376

__global__ __launch_bounds__(256, 1) void snn_main_kernel(
    const float* __restrict__ x,
    const float* __restrict__ W_in,  const float* __restrict__ b_in,
    const float* __restrict__ beta_in, const float* __restrict__ thr_in,
    const float* __restrict__ b_h,   const float* __restrict__ beta_h, const float* __restrict__ thr_h,
    const float* __restrict__ b_h2,  const float* __restrict__ beta_h2, const float* __restrict__ thr_h2,
    const float* __restrict__ W_out, const float* __restrict__ b_out, const float* __restrict__ beta_out)
{
    extern __shared__ __align__(16) char dsm[];
    __half* sA  = (__half*)(dsm + SMEM_SA);
    __half* sB  = (__half*)(dsm + SMEM_SB);
    float*  m1s = (float*)(dsm + SMEM_M1);     // [b][j] thread-private slots
    float*  xs  = (float*)(dsm + SMEM_XS);     // [2][BC*3]
    float*  red = (float*)(dsm + SMEM_RED);    // [BC][2][8]

    const int tid   = threadIdx.x;
    const int warp  = tid >> 5;
    const int lane  = tid & 31;
    const int g     = lane >> 2, q = lane & 3;
    const int bbase = blockIdx.x * BC;
    const int nbase = warp * 32;

    // layer-1 per-neuron constants (thread = neuron j)
    const int   j   = tid;
    const float Wi0 = W_in[j * 3 + 0], Wi1 = W_in[j * 3 + 1], Wi2 = W_in[j * 3 + 2];
    const float bin = b_in[j];
    const float betaIn = clip01(beta_in[j]);
    const float thrIn  = thr_in[j];

    float m2[32], m4[32];
#pragma unroll
    for (int i = 0; i < 32; ++i) { m2[i] = 0.f; m4[i] = 0.f; }
#pragma unroll
    for (int b = 0; b < BC; ++b) m1s[b * HH + j] = 0.f;

    // output-layer finisher (tid < 64): (b, o) = (tid>>1, tid&1)
    float m3r = 0.f, betaOutC = 0.f, bo = 0.f;
    const int fb = tid >> 1, fo = tid & 1;
    if (tid < 2 * BC) {
        betaOutC = clip01(beta_out[fo]);
        bo = b_out[fo];
    }

    const uint2* packL2h = d_Wpack;               // layer2 hi (L1-pinned)
    const uint2* packL2l = d_Wpack + 16384;       // layer2 lo
    const uint2* packL3h = d_Wpack + 32768;       // layer3 hi
    const uint2* packL3l = d_Wpack + 49152;       // layer3 lo

    // preload x(t=0)
    float xreg = 0.f;
    if (tid < BC * 3) xreg = x[(size_t)bbase * 3 + tid];

#pragma unroll 1
    for (int t = 0; t < TT; ++t) {
        if (tid < BC * 3) xs[(t & 1) * (BC * 3) + tid] = xreg;
        __syncthreads();                           // xs visible; red consumers done
        if (tid < BC * 3 && t + 1 < TT)
            xreg = x[((size_t)(t + 1) * BB + bbase) * 3 + tid];

        const float embt = d_emb[t];
        const float* xv = xs + (t & 1) * (BC * 3);

        // ---- layer 1 (input LIF), write spikes to sA ----
#pragma unroll
        for (int b = 0; b < BC; ++b) {
            float c1 = embt * (xv[b * 3] * Wi0 + xv[b * 3 + 1] * Wi1 + xv[b * 3 + 2] * Wi2) + bin;
            float mo = m1s[b * HH + j];
            float mn = betaIn * mo + c1 - ((mo > thrIn) ? thrIn : 0.f);
            m1s[b * HH + j] = mn;
            sA[b * SA_STRIDE + j] = __float2half_rn((mn > thrIn) ? 1.f : 0.f);
        }
        __syncthreads();                           // sA ready

        // ---- layer 2: HMMA GEMM + LIF -> sB (hi stream L1-pinned) ----
        layer_gemm<true, true>(sA, sB, nullptr, m2, packL2h, packL2l,
                               b_h, beta_h, thr_h, lane, nbase);
        __syncthreads();                           // sB ready

        // ---- layer 3: HMMA GEMM + LIF -> spikes in regs ----
        float sp[32];
        layer_gemm<false, false>(sB, nullptr, sp, m4, packL3h, packL3l,
                                 b_h2, beta_h2, thr_h2, lane, nbase);

        // ---- output partials: reduce this warp's n-range ----
#pragma unroll
        for (int mt = 0; mt < 2; ++mt)
#pragma unroll
            for (int rh = 0; rh < 2; ++rh) {
                float p0 = 0.f, p1 = 0.f;
#pragma unroll
                for (int nt = 0; nt < 4; ++nt) {
                    int n0 = nbase + nt * 8 + q * 2;
                    float2 w0 = *(const float2*)(W_out + n0);
                    float2 w1 = *(const float2*)(W_out + HH + n0);
                    int i0 = (mt * 4 + nt) * 4 + rh * 2;
                    p0 += sp[i0] * w0.x + sp[i0 + 1] * w0.y;
                    p1 += sp[i0] * w1.x + sp[i0 + 1] * w1.y;
                }
                p0 += __shfl_xor_sync(0xffffffffu, p0, 1);
                p0 += __shfl_xor_sync(0xffffffffu, p0, 2);
                p1 += __shfl_xor_sync(0xffffffffu, p1, 1);
                p1 += __shfl_xor_sync(0xffffffffu, p1, 2);
                if (q == 0) {
                    int row = mt * 16 + g + rh * 8;
                    red[(row * 2 + 0) * 8 + warp] = p0;
                    red[(row * 2 + 1) * 8 + warp] = p1;
                }
            }
        __syncthreads();                           // red ready

        // ---- leaky integrator (no reset), record spk & mem ----
        if (tid < 2 * BC) {
            float co = bo;
#pragma unroll
            for (int w = 0; w < 8; ++w) co += red[(fb * 2 + fo) * 8 + w];
            m3r = betaOutC * m3r + co;
            float spk = (m3r > 1.0f) ? 1.f : 0.f;
            size_t base = ((size_t)t * BB + bbase + fb) * 4;
            d_val[base + fo]     = spk;
            d_val[base + 2 + fo] = m3r;
        }
    }
}

// ---------------------------------------------------------------------------
// Final projection: flat d_val IS the reshaped [B, T*4] matrix.
// ---------------------------------------------------------------------------
__global__ void proj_kernel(const float* __restrict__ W_pred,
                            const float* __restrict__ b_pred,
                            float* __restrict__ out)
{
    int row  = blockIdx.x * 8 + (threadIdx.x >> 5);
    int lane = threadIdx.x & 31;
    const float* v = d_val + (size_t)row * 256;
    float p0 = 0.f, p1 = 0.f;
#pragma unroll
    for (int c = lane; c < 256; c += 32) {
        float vv = v[c];
        p0 += vv * W_pred[c];
        p1 += vv * W_pred[256 + c];
    }
#pragma unroll
    for (int off = 16; off > 0; off >>= 1) {
        p0 += __shfl_down_sync(0xffffffffu, p0, off);
        p1 += __shfl_down_sync(0xffffffffu, p1, off);
    }
    if (lane == 0) {
        out[row * 2 + 0] = p0 + b_pred[0];
        out[row * 2 + 1] = p1 + b_pred[1];
    }
}

// ---------------------------------------------------------------------------
extern "C" void kernel_launch(void* const* d_in, const int* in_sizes, int n_in,
                              void* d_out, int out_size)
{
    const float* x       = (const float*)d_in[0];
    const float* W_in    = (const float*)d_in[1];
    const float* b_in    = (const float*)d_in[2];
    const float* beta_in = (const float*)d_in[3];
    const float* thr_in  = (const float*)d_in[4];
    const float* W_h     = (const float*)d_in[5];
    const float* b_h     = (const float*)d_in[6];
    const float* beta_h  = (const float*)d_in[7];
    const float* thr_h   = (const float*)d_in[8];
    const float* W_h2    = (const float*)d_in[9];
    const float* b_h2    = (const float*)d_in[10];
    const float* beta_h2 = (const float*)d_in[11];
    const float* thr_h2  = (const float*)d_in[12];
    const float* W_out   = (const float*)d_in[13];
    const float* b_out   = (const float*)d_in[14];
    const float* beta_out= (const float*)d_in[15];
    const float* W_pred  = (const float*)d_in[16];
    const float* b_pred  = (const float*)d_in[17];
    float* out = (float*)d_out;

    cudaFuncSetAttribute(snn_main_kernel,
                         cudaFuncAttributeMaxDynamicSharedMemorySize, SMEM_TOTAL);

    prep_kernel<<<256, 256>>>(W_h, W_h2);
    snn_main_kernel<<<NCTA, 256, SMEM_TOTAL>>>(x, W_in, b_in, beta_in, thr_in,
                                               b_h, beta_h, thr_h,
                                               b_h2, beta_h2, thr_h2,
                                               W_out, b_out, beta_out);
    proj_kernel<<<BB / 8, 256>>>(W_pred, b_pred, out);
}